// round 7
// baseline (speedup 1.0000x reference)
#include <cuda_runtime.h>
#include <stdint.h>

// Problem constants
#define NUM_BOXES    512
#define NUM_COORDS   200000
#define FEAT_C       128
#define MAX_SELECTED 262144
#define N_ELEMS      (NUM_BOXES * NUM_COORDS)   // 102,400,000 mask elements
#define THREADS      256
#define ELEMS_PER_TH 32
#define ELEMS_PER_BLK (THREADS * ELEMS_PER_TH)  // 8192
#define NBLK         (N_ELEMS / ELEMS_PER_BLK)  // 12500 exactly

// Decoupled-lookback descriptor: bits 31:30 flag, bits 29:0 value.
#define FLAG_INVALID 0u
#define FLAG_AGG     (1u << 30)
#define FLAG_PREFIX  (2u << 30)
#define VAL_MASK     0x3FFFFFFFu

// Scratch (device globals — no allocation allowed)
__device__ unsigned g_desc[NBLK];
__device__ int g_count;
__device__ unsigned g_nonconform = 0;  // 1 => byte-bools; 0 => 32-bit elems

// ---------------------------------------------------------------------------
// Prep: zero lookback descriptors (every replay) + mode detection.
// Word-mode masks contain only {0, 1, 0x3F800000} words.
// ---------------------------------------------------------------------------
__global__ void k_prep(const unsigned* __restrict__ w) {
    int i = blockIdx.x * blockDim.x + threadIdx.x;
    if (i < NBLK) g_desc[i] = FLAG_INVALID;
    unsigned bad = 0;
    for (unsigned j = i; j < (1u << 20); j += gridDim.x * blockDim.x) {
        unsigned v = w[j];
        if (v != 0u && v != 1u && v != 0x3F800000u) bad = 1u;
    }
    if (bad) g_nonconform = 1u;  // monotone, input-determined: replay-safe
}

// Load this thread's 32 contiguous elements; return count of set elements.
__device__ __forceinline__ int load_count(const void* mask, int blk, int tid,
                                          int byte_mode, uint4 v[8]) {
    if (byte_mode) {
        const uint4* p = (const uint4*)mask + (size_t)blk * 512 + (size_t)tid * 2;
        unsigned a = 0;
#pragma unroll
        for (int i = 0; i < 2; i++) {
            v[i] = p[i];                     // 16 bytes each
            a = __dp4a(v[i].x, 0x01010101u, a);
            a = __dp4a(v[i].y, 0x01010101u, a);
            a = __dp4a(v[i].z, 0x01010101u, a);
            a = __dp4a(v[i].w, 0x01010101u, a);
        }
        return (int)a;
    } else {
        const uint4* p = (const uint4*)mask + (size_t)blk * 2048 + (size_t)tid * 8;
        int c = 0;
#pragma unroll
        for (int i = 0; i < 8; i++) {
            v[i] = p[i];                     // 16 words each
            c += (v[i].x != 0u) + (v[i].y != 0u) + (v[i].z != 0u) + (v[i].w != 0u);
        }
        return c;
    }
}

// ---------------------------------------------------------------------------
// Fused single-pass: block scan + decoupled lookback + ordered emit of
// both the ext-coord row AND the 128-float feature row.
// ---------------------------------------------------------------------------
__global__ void k_fused(const void* __restrict__ mask,
                        const int4* __restrict__ coords,
                        const float4* __restrict__ feat,
                        float4* __restrict__ out_ext,
                        float4* __restrict__ out_feat) {
    const int blk = blockIdx.x, tid = threadIdx.x;
    const int lane = tid & 31, wrp = tid >> 5;
    const int byte_mode = (g_nonconform != 0u);

    uint4 v[8];
    int cnt = load_count(mask, blk, tid, byte_mode, v);

    // warp inclusive scan
    int incl = cnt;
#pragma unroll
    for (int o = 1; o < 32; o <<= 1) {
        int t = __shfl_up_sync(0xFFFFFFFFu, incl, o);
        if (lane >= o) incl += t;
    }
    __shared__ int ws[8];
    __shared__ int s_excl;
    if (lane == 31) ws[wrp] = incl;
    __syncthreads();

    int wbase = 0, total = 0;
#pragma unroll
    for (int i = 0; i < 8; i++) {
        int w = ws[i];
        wbase += (i < wrp) ? w : 0;
        total += w;
    }

    // Publish status
    if (tid == 0) {
        if (blk == 0) {
            atomicExch(&g_desc[0], FLAG_PREFIX | (unsigned)total);
            s_excl = 0;
            if (blk == NBLK - 1) g_count = total;
        } else {
            atomicExch(&g_desc[blk], FLAG_AGG | (unsigned)total);
        }
    }

    // Warp 0 lookback
    if (wrp == 0 && blk > 0) {
        int excl = 0;
        int k = blk - 1;
        while (true) {
            int idx = k - lane;
            unsigned s = (idx >= 0) ? atomicAdd(&g_desc[idx], 0u)
                                    : (FLAG_PREFIX | 0u);
            unsigned flag = s & 0xC0000000u;
            unsigned val  = s & VAL_MASK;
            unsigned bP = __ballot_sync(0xFFFFFFFFu, flag == FLAG_PREFIX);
            unsigned bI = __ballot_sync(0xFFFFFFFFu, flag == FLAG_INVALID);
            int firstP = bP ? (__ffs(bP) - 1) : 32;
            int firstI = bI ? (__ffs(bI) - 1) : 32;

            if (firstP < firstI) {
                unsigned contrib = (lane <= firstP) ? val : 0u;
#pragma unroll
                for (int o = 16; o; o >>= 1)
                    contrib += __shfl_xor_sync(0xFFFFFFFFu, contrib, o);
                excl += (int)contrib;
                break;
            } else if (firstI > 0) {
                unsigned contrib = (lane < firstI) ? val : 0u;
#pragma unroll
                for (int o = 16; o; o >>= 1)
                    contrib += __shfl_xor_sync(0xFFFFFFFFu, contrib, o);
                excl += (int)contrib;
                k -= firstI;
            } else {
                __nanosleep(60);
            }
        }
        if (lane == 0) {
            s_excl = excl;
            atomicExch(&g_desc[blk], FLAG_PREFIX | (unsigned)(excl + total));
            if (blk == NBLK - 1) g_count = excl + total;
        }
    }
    __syncthreads();

    int pout = s_excl + wbase + (incl - cnt);
    const int ebase = blk * ELEMS_PER_BLK + tid * ELEMS_PER_TH;

    auto emit_one = [&](int elem) {
        if (pout < MAX_SELECTED) {
            int coord = elem % NUM_COORDS;
            int box   = elem / NUM_COORDS;
            int4 c = coords[coord];
            out_ext[pout] = make_float4((float)c.x, (float)c.y,
                                        (float)c.z, (float)box);
            // Copy the 128-float feature row (32 x float4), unrolled for MLP.
            const float4* src = feat + (size_t)coord * 32;
            float4* dst = out_feat + (size_t)pout * 32;
#pragma unroll 8
            for (int q = 0; q < 32; q++) dst[q] = src[q];
        }
        pout++;
    };

    if (byte_mode) {
#pragma unroll
        for (int i = 0; i < 2; i++) {
            unsigned words[4] = { v[i].x, v[i].y, v[i].z, v[i].w };
#pragma unroll
            for (int j = 0; j < 4; j++) {
                unsigned w32 = words[j];
                if (w32 == 0u) continue;
#pragma unroll
                for (int b = 0; b < 4; b++)
                    if ((w32 >> (8 * b)) & 0xFFu)
                        emit_one(ebase + i * 16 + j * 4 + b);
            }
        }
    } else {
#pragma unroll
        for (int i = 0; i < 8; i++) {
            unsigned words[4] = { v[i].x, v[i].y, v[i].z, v[i].w };
#pragma unroll
            for (int j = 0; j < 4; j++)
                if (words[j] != 0u) emit_one(ebase + i * 4 + j);
        }
    }
}

// ---------------------------------------------------------------------------
// Tail: zero rows [count, MAX_SELECTED) — ext + features. Warp per row.
// ---------------------------------------------------------------------------
__global__ void k_tail(float4* __restrict__ out_ext,
                       float4* __restrict__ out_feat) {
    const int gw   = (int)((blockIdx.x * (unsigned)blockDim.x + threadIdx.x) >> 5);
    const int lane = threadIdx.x & 31;
    if (gw >= MAX_SELECTED || gw < g_count) return;
    out_feat[(size_t)gw * 32 + lane] = make_float4(0.f, 0.f, 0.f, 0.f);
    if (lane == 0) out_ext[gw] = make_float4(0.f, 0.f, 0.f, 0.f);
}

// ---------------------------------------------------------------------------
extern "C" void kernel_launch(void* const* d_in, const int* in_sizes, int n_in,
                              void* d_out, int out_size) {
    const int4*   coords = nullptr;
    const float4* feat   = nullptr;
    const void*   mask   = nullptr;
    for (int i = 0; i < n_in; i++) {
        if (in_sizes[i] == NUM_COORDS * 4)           coords = (const int4*)d_in[i];
        else if (in_sizes[i] == NUM_COORDS * FEAT_C) feat   = (const float4*)d_in[i];
        else if (in_sizes[i] == N_ELEMS)             mask   = d_in[i];
    }
    (void)out_size;

    float* out = (float*)d_out;
    float4* out_ext  = (float4*)out;                              // [262144,4] as floats
    float4* out_feat = (float4*)(out + 4 * (size_t)MAX_SELECTED); // [262144,128]

    k_prep<<<4096, 256>>>((const unsigned*)mask);
    k_fused<<<NBLK, THREADS>>>(mask, coords, feat, out_ext, out_feat);
    k_tail<<<MAX_SELECTED * 32 / 256, 256>>>(out_ext, out_feat);
}

// round 9
// speedup vs baseline: 1.4600x; 1.4600x over previous
#include <cuda_runtime.h>
#include <stdint.h>

// Problem constants
#define NUM_COORDS   200000
#define FEAT_C       128
#define MAX_SELECTED 262144
#define N_ELEMS      (512 * NUM_COORDS)         // 102,400,000 mask elements
#define THREADS      256
#define ELEMS_PER_TH 32
#define ELEMS_PER_BLK (THREADS * ELEMS_PER_TH)  // 8192
#define NBLK         (N_ELEMS / ELEMS_PER_BLK)  // 12500 exactly
#define SENTINEL     THREADS                    // MUST equal lookback window size!

// Decoupled-lookback descriptor: bits 31:30 flag, bits 29:0 value.
#define FLAG_INVALID 0u
#define FLAG_AGG     (1u << 30)
#define FLAG_PREFIX  (2u << 30)
#define VAL_MASK     0x3FFFFFFFu

// Scratch. g_desc starts zero-initialized (INVALID) and is reset by k_gather
// after every fused run, so each graph replay sees a clean state.
__device__ unsigned g_desc[NBLK];
__device__ int g_count;
__device__ int g_selidx[MAX_SELECTED];
__device__ unsigned g_nonconform = 0;  // 1 => byte-bools; 0 => 32-bit elems

// ---------------------------------------------------------------------------
// Mode detection (1 MB scan). Word-mode masks contain only {0,1,0x3F800000}.
// Monotone + input-determined => replay-safe without reset.
// ---------------------------------------------------------------------------
__global__ void k_detect(const unsigned* __restrict__ w) {
    unsigned i = blockIdx.x * blockDim.x + threadIdx.x;
    unsigned bad = 0;
    for (unsigned j = i; j < (1u << 18); j += gridDim.x * blockDim.x) {
        unsigned v = w[j];
        if (v != 0u && v != 1u && v != 0x3F800000u) bad = 1u;
    }
    if (bad) g_nonconform = 1u;
}

// Load this thread's 32 contiguous elements; return count of set elements.
__device__ __forceinline__ int load_count(const void* mask, int blk, int tid,
                                          int byte_mode, uint4 v[8]) {
    if (byte_mode) {
        const uint4* p = (const uint4*)mask + (size_t)blk * 512 + (size_t)tid * 2;
        unsigned a = 0;
#pragma unroll
        for (int i = 0; i < 2; i++) {
            v[i] = p[i];
            a = __dp4a(v[i].x, 0x01010101u, a);
            a = __dp4a(v[i].y, 0x01010101u, a);
            a = __dp4a(v[i].z, 0x01010101u, a);
            a = __dp4a(v[i].w, 0x01010101u, a);
        }
        return (int)a;
    } else {
        const uint4* p = (const uint4*)mask + (size_t)blk * 2048 + (size_t)tid * 8;
        int c = 0;
#pragma unroll
        for (int i = 0; i < 8; i++) {
            v[i] = p[i];
            c += (v[i].x != 0u) + (v[i].y != 0u) + (v[i].z != 0u) + (v[i].w != 0u);
        }
        return c;
    }
}

// ---------------------------------------------------------------------------
// Fused single-pass: block scan + block-wide (256-lane) decoupled lookback +
// ordered light emit (ext coords as float values + selidx).
// ---------------------------------------------------------------------------
__global__ void k_fused(const void* __restrict__ mask,
                        const int4* __restrict__ coords,
                        float4* __restrict__ out_ext) {
    const int blk = blockIdx.x, tid = threadIdx.x;
    const int lane = tid & 31, wrp = tid >> 5;
    const int byte_mode = (g_nonconform != 0u);

    uint4 v[8];
    int cnt = load_count(mask, blk, tid, byte_mode, v);

    // warp inclusive scan of per-thread counts
    int incl = cnt;
#pragma unroll
    for (int o = 1; o < 32; o <<= 1) {
        int t = __shfl_up_sync(0xFFFFFFFFu, incl, o);
        if (lane >= o) incl += t;
    }
    __shared__ int ws[8];
    if (lane == 31) ws[wrp] = incl;
    __syncthreads();

    int wbase = 0, total = 0;
#pragma unroll
    for (int i = 0; i < 8; i++) {
        int w = ws[i];
        wbase += (i < wrp) ? w : 0;
        total += w;
    }

    // Publish this block's status
    if (tid == 0) {
        if (blk == 0) {
            atomicExch(&g_desc[0], FLAG_PREFIX | (unsigned)total);
            if (blk == NBLK - 1) g_count = total;
        } else {
            atomicExch(&g_desc[blk], FLAG_AGG | (unsigned)total);
        }
    }

    // Block-wide lookback: up to 256 descriptors per round.
    // SENTINEL == window size (256): "no flag in window" must consume exactly
    // the window, no more (R8 bug: sentinel 4096 skipped unconsumed blocks).
    int excl = 0;
    if (blk > 0) {
        __shared__ int sw_firstP[8], sw_firstI[8], sw_sum[8];
        int k = blk - 1;
        while (true) {
            int idx = k - tid;
            unsigned s = (idx >= 0) ? atomicAdd(&g_desc[idx], 0u)
                                    : (FLAG_PREFIX | 0u);
            unsigned flag = s & 0xC0000000u;
            int val = (int)(s & VAL_MASK);

            unsigned bP = __ballot_sync(0xFFFFFFFFu, flag == FLAG_PREFIX);
            unsigned bI = __ballot_sync(0xFFFFFFFFu, flag == FLAG_INVALID);
            if (lane == 0) {
                sw_firstP[wrp] = bP ? (wrp * 32 + __ffs(bP) - 1) : SENTINEL;
                sw_firstI[wrp] = bI ? (wrp * 32 + __ffs(bI) - 1) : SENTINEL;
            }
            __syncthreads();
            int firstP = SENTINEL, firstI = SENTINEL;
#pragma unroll
            for (int i = 0; i < 8; i++) {
                firstP = min(firstP, sw_firstP[i]);
                firstI = min(firstI, sw_firstI[i]);
            }
            // entries consumable this round (<= window size by construction)
            int limit = (firstP < firstI) ? (firstP + 1) : firstI;

            int c = (tid < limit) ? val : 0;
#pragma unroll
            for (int o = 16; o; o >>= 1) c += __shfl_xor_sync(0xFFFFFFFFu, c, o);
            if (lane == 0) sw_sum[wrp] = c;
            __syncthreads();
            int tot = 0;
#pragma unroll
            for (int i = 0; i < 8; i++) tot += sw_sum[i];
            excl += tot;

            if (firstP < firstI) break;       // hit a PREFIX: done
            if (firstI > 0) k -= firstI;      // consumed firstI aggregates
            else __nanosleep(40);             // window head still INVALID
            __syncthreads();                  // protect smem reuse next round
        }
        if (tid == 0) {
            atomicExch(&g_desc[blk], FLAG_PREFIX | (unsigned)(excl + total));
            if (blk == NBLK - 1) g_count = excl + total;
        }
    }

    int pout = excl + wbase + (incl - cnt);
    const int ebase = blk * ELEMS_PER_BLK + tid * ELEMS_PER_TH;

    auto emit_one = [&](int elem) {
        if (pout < MAX_SELECTED) {
            int coord = elem % NUM_COORDS;
            int box   = elem / NUM_COORDS;
            g_selidx[pout] = coord;
            int4 c = coords[coord];
            out_ext[pout] = make_float4((float)c.x, (float)c.y,
                                        (float)c.z, (float)box);
        }
        pout++;
    };

    if (byte_mode) {
#pragma unroll
        for (int i = 0; i < 2; i++) {
            unsigned words[4] = { v[i].x, v[i].y, v[i].z, v[i].w };
#pragma unroll
            for (int j = 0; j < 4; j++) {
                unsigned w32 = words[j];
                if (w32 == 0u) continue;
#pragma unroll
                for (int b = 0; b < 4; b++)
                    if ((w32 >> (8 * b)) & 0xFFu)
                        emit_one(ebase + i * 16 + j * 4 + b);
            }
        }
    } else {
#pragma unroll
        for (int i = 0; i < 8; i++) {
            unsigned words[4] = { v[i].x, v[i].y, v[i].z, v[i].w };
#pragma unroll
            for (int j = 0; j < 4; j++)
                if (words[j] != 0u) emit_one(ebase + i * 4 + j);
        }
    }
}

// ---------------------------------------------------------------------------
// Gather: warp-per-row feature copy + zero tail. Also resets g_desc for the
// next graph replay (safe: stream-ordered after k_fused).
// ---------------------------------------------------------------------------
__global__ void k_gather(const float4* __restrict__ feat,
                         float4* __restrict__ out_ext,
                         float4* __restrict__ out_feat) {
    const int gt = blockIdx.x * blockDim.x + threadIdx.x;
    if (gt < NBLK) g_desc[gt] = FLAG_INVALID;

    const int gw   = gt >> 5;
    const int lane = threadIdx.x & 31;
    if (gw >= MAX_SELECTED) return;
    if (gw < g_count) {
        int c = g_selidx[gw];
        out_feat[(size_t)gw * 32 + lane] = feat[(size_t)c * 32 + lane];
    } else {
        out_feat[(size_t)gw * 32 + lane] = make_float4(0.f, 0.f, 0.f, 0.f);
        if (lane == 0) out_ext[gw] = make_float4(0.f, 0.f, 0.f, 0.f);
    }
}

// ---------------------------------------------------------------------------
extern "C" void kernel_launch(void* const* d_in, const int* in_sizes, int n_in,
                              void* d_out, int out_size) {
    const int4*   coords = nullptr;
    const float4* feat   = nullptr;
    const void*   mask   = nullptr;
    for (int i = 0; i < n_in; i++) {
        if (in_sizes[i] == NUM_COORDS * 4)           coords = (const int4*)d_in[i];
        else if (in_sizes[i] == NUM_COORDS * FEAT_C) feat   = (const float4*)d_in[i];
        else if (in_sizes[i] == N_ELEMS)             mask   = d_in[i];
    }
    (void)out_size;

    float* out = (float*)d_out;
    float4* out_ext  = (float4*)out;                              // [262144,4] as floats
    float4* out_feat = (float4*)(out + 4 * (size_t)MAX_SELECTED); // [262144,128]

    k_detect<<<512, 256>>>((const unsigned*)mask);
    k_fused<<<NBLK, THREADS>>>(mask, coords, out_ext);
    k_gather<<<MAX_SELECTED * 32 / 256, 256>>>(feat, out_ext, out_feat);
}